// round 3
// baseline (speedup 1.0000x reference)
#include <cuda_runtime.h>
#include <cuda_bf16.h>

#define FEATS 64
#define N_SRC_MAX 100000
#define TILE_ROWS 128
#define KCH 16

// Scratch (device globals: no allocation allowed in kernel_launch)
__device__ float g_summed[(size_t)N_SRC_MAX * FEATS];
__device__ float g_deg[N_SRC_MAX];

// ---------------------------------------------------------------------------
// Kernel 1: zero the accumulators (graph is replayed; must re-zero each launch)
// ---------------------------------------------------------------------------
__global__ void sage_init_kernel(int num_dst) {
    int stride = gridDim.x * blockDim.x;
    int i = blockIdx.x * blockDim.x + threadIdx.x;
    int total4 = num_dst * (FEATS / 4);
    float4 z = make_float4(0.f, 0.f, 0.f, 0.f);
    for (int idx = i; idx < total4; idx += stride)
        reinterpret_cast<float4*>(g_summed)[idx] = z;
    for (int idx = i; idx < num_dst; idx += stride)
        g_deg[idx] = 0.f;
}

// ---------------------------------------------------------------------------
// Kernel 2: edge scatter.  16 threads per edge, one float4 (16B) each.
// red.global.add.v4.f32 -> 16M vector reductions instead of 64M scalars.
// x (25.6MB) + g_summed (25.6MB) are L2-resident -> LTS-bound phase.
// Grid-stride persistent form.
// ---------------------------------------------------------------------------
__global__ __launch_bounds__(256) void sage_scatter_kernel(
    const float* __restrict__ x,
    const int* __restrict__ src,
    const int* __restrict__ dst,
    int n_edges) {
    const long long total = (long long)n_edges * 16;
    const long long stride = (long long)gridDim.x * blockDim.x;
    for (long long gid = (long long)blockIdx.x * blockDim.x + threadIdx.x;
         gid < total; gid += stride) {
        const int e = (int)(gid >> 4);
        const int c = (int)(gid & 15);

        const int s = __ldg(src + e);   // same-addr broadcast within 16-lane group
        const int d = __ldg(dst + e);

        float4 v = __ldg(reinterpret_cast<const float4*>(x + (size_t)s * FEATS) + c);
        float* p = g_summed + (size_t)d * FEATS + c * 4;
        asm volatile("red.global.add.v4.f32 [%0], {%1,%2,%3,%4};"
                     :: "l"(p), "f"(v.x), "f"(v.y), "f"(v.z), "f"(v.w)
                     : "memory");
        if (c == 0) atomicAdd(g_deg + d, 1.0f);
    }
}

// ---------------------------------------------------------------------------
// Kernel 3: fused GEMM + bias + relu.
//   h = [x_row | summed_row * inv_deg] (1x128)  @  [W_self ; W_neigh] (128x64)
// Block: 256 threads, 128-row tile, each thread computes 8 rows x 4 cols.
// W (128x64 f32, k-major) lives in shared for the whole block.
// A is staged in shared in K-chunks of 16.
// ---------------------------------------------------------------------------
__global__ __launch_bounds__(256) void sage_gemm_kernel(
    const float* __restrict__ x,
    const float* __restrict__ Wself,
    const float* __restrict__ Wneigh,
    const float* __restrict__ bias,
    float* __restrict__ out,
    int n_rows) {

    __shared__ float Wsh[128][64];        // [k][c]; k<64 -> W_self, k>=64 -> W_neigh
    __shared__ float Ash[TILE_ROWS][20];  // [row][k within chunk], pad 20 keeps 16B align
    __shared__ float invd[TILE_ROWS];
    __shared__ float bsh[64];

    const int tid = threadIdx.x;
    const int row0 = blockIdx.x * TILE_ROWS;

    // Load combined W into shared (k-major). W_self/W_neigh are [k][c] row-major.
    for (int i = tid; i < 64 * 64; i += 256) {
        int k = i >> 6, c = i & 63;
        Wsh[k][c]      = __ldg(Wself + i);
        Wsh[k + 64][c] = __ldg(Wneigh + i);
    }
    if (tid < 64) bsh[tid] = __ldg(bias + tid);
    if (tid < TILE_ROWS) {
        int r = row0 + tid;
        float dg = (r < n_rows) ? g_deg[r] : 1.f;
        invd[tid] = 1.0f / fmaxf(dg, 1.0f);
    }
    __syncthreads();

    const int cg = tid & 15;   // column group: cols cg*4 .. cg*4+3
    const int rg = tid >> 4;   // row group:    rows rg*8 .. rg*8+7

    float acc[8][4];
#pragma unroll
    for (int i = 0; i < 8; i++)
#pragma unroll
        for (int j = 0; j < 4; j++) acc[i][j] = 0.f;

    for (int kb = 0; kb < 128; kb += KCH) {
        // Stage A chunk: each thread loads 8 floats (2x float4).
        // r = tid/2, k-offset = (tid&1)*8
        {
            const int r = tid >> 1;
            const int ko = (tid & 1) * 8;
            const int grow = row0 + r;
            const float s = invd[r];
#pragma unroll
            for (int j = 0; j < 2; j++) {
                const int kk = kb + ko + j * 4;
                float4 v;
                if (grow < n_rows) {
                    if (kk < 64) {
                        v = *reinterpret_cast<const float4*>(x + (size_t)grow * 64 + kk);
                    } else {
                        v = *reinterpret_cast<const float4*>(g_summed + (size_t)grow * 64 + (kk - 64));
                        v.x *= s; v.y *= s; v.z *= s; v.w *= s;
                    }
                } else {
                    v = make_float4(0.f, 0.f, 0.f, 0.f);
                }
                *reinterpret_cast<float4*>(&Ash[r][ko + j * 4]) = v;
            }
        }
        __syncthreads();

#pragma unroll
        for (int k = 0; k < KCH; k++) {
            const float4 b4 = *reinterpret_cast<const float4*>(&Wsh[kb + k][cg * 4]);
#pragma unroll
            for (int i = 0; i < 8; i++) {
                const float a = Ash[rg * 8 + i][k];
                acc[i][0] = fmaf(a, b4.x, acc[i][0]);
                acc[i][1] = fmaf(a, b4.y, acc[i][1]);
                acc[i][2] = fmaf(a, b4.z, acc[i][2]);
                acc[i][3] = fmaf(a, b4.w, acc[i][3]);
            }
        }
        __syncthreads();
    }

    // Epilogue: bias + relu, vectorized store
    const float4 bb = *reinterpret_cast<const float4*>(&bsh[cg * 4]);
#pragma unroll
    for (int i = 0; i < 8; i++) {
        const int r = row0 + rg * 8 + i;
        if (r < n_rows) {
            float4 o;
            o.x = fmaxf(acc[i][0] + bb.x, 0.f);
            o.y = fmaxf(acc[i][1] + bb.y, 0.f);
            o.z = fmaxf(acc[i][2] + bb.z, 0.f);
            o.w = fmaxf(acc[i][3] + bb.w, 0.f);
            *reinterpret_cast<float4*>(out + (size_t)r * 64 + cg * 4) = o;
        }
    }
}

// ---------------------------------------------------------------------------
// Launch. Inputs (metadata order): x, W_self, W_neigh, b, src, dst, num_dst
// ---------------------------------------------------------------------------
extern "C" void kernel_launch(void* const* d_in, const int* in_sizes, int n_in,
                              void* d_out, int out_size) {
    const float* x      = (const float*)d_in[0];
    const float* Wself  = (const float*)d_in[1];
    const float* Wneigh = (const float*)d_in[2];
    const float* bias   = (const float*)d_in[3];
    const int*   src    = (const int*)d_in[4];
    const int*   dst    = (const int*)d_in[5];

    const int n_src   = in_sizes[0] / FEATS;
    const int n_edges = in_sizes[4];
    const int num_dst = n_src;   // per problem spec (num_dst == N_SRC)
    float* out = (float*)d_out;

    sage_init_kernel<<<1024, 256>>>(num_dst);

    sage_scatter_kernel<<<2368, 256>>>(x, src, dst, n_edges);

    {
        const int blocks = (num_dst + TILE_ROWS - 1) / TILE_ROWS;
        sage_gemm_kernel<<<blocks, 256>>>(x, Wself, Wneigh, bias, out, num_dst);
    }
}